// round 1
// baseline (speedup 1.0000x reference)
#include <cuda_runtime.h>
#include <stdint.h>

typedef unsigned long long ull;

#define TOKENS 16384
#define DIM    256
#define KW     8192

#define BM   128      // tokens per block
#define BN   128      // weights per chunk
#define BK   32       // d per smem stage
#define SPLIT 8       // K-split factor
#define KRANGE (KW / SPLIT)
#define SW   130      // padded smem row width (floats), even (LDS.64 align), 2-way max conflicts

__device__ float g_wn[KW];
__device__ float g_pval[TOKENS * SPLIT];
__device__ int   g_pidx[TOKENS * SPLIT];

// ---------------- weight norms ----------------
__global__ void wnorm_kernel(const float* __restrict__ w) {
    int k = blockIdx.x * 256 + threadIdx.x;
    const float4* row = (const float4*)(w + (size_t)k * DIM);
    float s = 0.f;
#pragma unroll
    for (int i = 0; i < DIM / 4; i++) {
        float4 v = row[i];
        s += v.x * v.x + v.y * v.y + v.z * v.z + v.w * v.w;
    }
    g_wn[k] = s;
}

// ---------------- main GEMM + streaming argmax ----------------
// grid: (TOKENS/BM, SPLIT); block: 128 threads (tx=0..15 weights-dim, ty=0..7 tokens-dim)
// thread tile: 16 tokens (8 f32x2 pairs) x 8 weights -> 64 packed accumulators
__global__ __launch_bounds__(128, 2)
void vq_argmax_kernel(const float* __restrict__ x, const float* __restrict__ wt) {
    __shared__ float xs[BK * SW];
    __shared__ float ws[BK * SW];

    const int tid = threadIdx.x;
    const int tx = tid & 15;
    const int ty = tid >> 4;
    const int mbase = blockIdx.x * BM;
    const int nbase0 = blockIdx.y * KRANGE;

    float bv[16];
    int   bi[16];
#pragma unroll
    for (int t = 0; t < 16; t++) { bv[t] = -3.402823e38f; bi[t] = 0x7fffffff; }

    for (int nc = 0; nc < KRANGE; nc += BN) {
        const int nbase = nbase0 + nc;

        ull acc[8][8];
#pragma unroll
        for (int p = 0; p < 8; p++)
#pragma unroll
            for (int j = 0; j < 8; j++) acc[p][j] = 0ull;

        for (int dt = 0; dt < DIM; dt += BK) {
            __syncthreads();
            // cooperative load + transpose: tile[row][d] -> smem[d][row]
            const int d4 = (tid & 7) * 4;
#pragma unroll
            for (int it = 0; it < 8; it++) {
                const int r = (tid >> 3) + 16 * it;   // 0..127
                float4 v = *(const float4*)(x + (size_t)(mbase + r) * DIM + dt + d4);
                xs[(d4 + 0) * SW + r] = v.x;
                xs[(d4 + 1) * SW + r] = v.y;
                xs[(d4 + 2) * SW + r] = v.z;
                xs[(d4 + 3) * SW + r] = v.w;
                float4 u = *(const float4*)(wt + (size_t)(nbase + r) * DIM + dt + d4);
                ws[(d4 + 0) * SW + r] = u.x;
                ws[(d4 + 1) * SW + r] = u.y;
                ws[(d4 + 2) * SW + r] = u.z;
                ws[(d4 + 3) * SW + r] = u.w;
            }
            __syncthreads();

#pragma unroll
            for (int k = 0; k < BK; k++) {
                ull x2[8];
#pragma unroll
                for (int p = 0; p < 8; p++)
                    x2[p] = *(const ull*)(&xs[k * SW + ty * 16 + 2 * p]);  // token pair, LDS.64 broadcast
                ull w2[8];
#pragma unroll
                for (int j = 0; j < 8; j++) {
                    float wv = ws[k * SW + tx + 16 * j];   // conflict-free strided
                    asm("mov.b64 %0, {%1, %1};" : "=l"(w2[j]) : "f"(wv));
                }
#pragma unroll
                for (int p = 0; p < 8; p++)
#pragma unroll
                    for (int j = 0; j < 8; j++)
                        asm("fma.rn.f32x2 %0, %1, %2, %0;"
                            : "+l"(acc[p][j]) : "l"(x2[p]), "l"(w2[j]));
            }
        }

        // chunk epilogue: score = ||w||^2 - 2 x.w ; streaming argmax (first-index tie-break)
#pragma unroll
        for (int j = 0; j < 8; j++) {
            const int n = nbase + tx + 16 * j;
            const float wn = g_wn[n];
#pragma unroll
            for (int p = 0; p < 8; p++) {
                float lo, hi;
                asm("mov.b64 {%0, %1}, %2;" : "=f"(lo), "=f"(hi) : "l"(acc[p][j]));
                const float s0 = wn - 2.f * lo;
                const float s1 = wn - 2.f * hi;
                const int t0 = 2 * p, t1 = 2 * p + 1;
                if (s0 > bv[t0] || (s0 == bv[t0] && n < bi[t0])) { bv[t0] = s0; bi[t0] = n; }
                if (s1 > bv[t1] || (s1 == bv[t1] && n < bi[t1])) { bv[t1] = s1; bi[t1] = n; }
            }
        }
    }

    // reduce across the 16 tx lanes (same ty within each 16-lane warp half)
#pragma unroll
    for (int off = 8; off >= 1; off >>= 1) {
#pragma unroll
        for (int t = 0; t < 16; t++) {
            float ov = __shfl_xor_sync(0xffffffffu, bv[t], off);
            int   oi = __shfl_xor_sync(0xffffffffu, bi[t], off);
            if (ov > bv[t] || (ov == bv[t] && oi < bi[t])) { bv[t] = ov; bi[t] = oi; }
        }
    }

    if (tx == 0) {
        const int s = blockIdx.y;
#pragma unroll
        for (int t = 0; t < 16; t++) {
            const int tok = mbase + ty * 16 + t;
            g_pval[tok * SPLIT + s] = bv[t];
            g_pidx[tok * SPLIT + s] = bi[t];
        }
    }
}

// ---------------- combine split partials + gather ----------------
// grid: TOKENS blocks x 64 threads; each thread redundantly reduces 8 partials (L2-hot),
// then the block copies the selected codebook row (64 x float4 = 256 floats).
__global__ void reduce_gather_kernel(const float* __restrict__ wt, float* __restrict__ out) {
    const int tok = blockIdx.x;
    float bv = -3.402823e38f;
    int   bi = 0x7fffffff;
#pragma unroll
    for (int s = 0; s < SPLIT; s++) {
        const float v = g_pval[tok * SPLIT + s];
        const int   i = g_pidx[tok * SPLIT + s];
        if (v > bv || (v == bv && i < bi)) { bv = v; bi = i; }
    }
    const float4 v = *(const float4*)(wt + (size_t)bi * DIM + threadIdx.x * 4);
    *(float4*)(out + (size_t)tok * DIM + threadIdx.x * 4) = v;
}

// ---------------- launch ----------------
extern "C" void kernel_launch(void* const* d_in, const int* in_sizes, int n_in,
                              void* d_out, int out_size) {
    const float* x  = (const float*)d_in[0];   // [16384, 256]
    const float* wt = (const float*)d_in[1];   // [8192, 256]
    float* out = (float*)d_out;                // [16384, 256]

    wnorm_kernel<<<KW / 256, 256>>>(wt);

    dim3 grid(TOKENS / BM, SPLIT);
    vq_argmax_kernel<<<grid, 128>>>(x, wt);

    reduce_gather_kernel<<<TOKENS, 64>>>(wt, out);
}